// round 14
// baseline (speedup 1.0000x reference)
#include <cuda_runtime.h>
#include <cuda_fp16.h>
#include <cstdint>

// ============================================================================
// Problem constants
// ============================================================================
static constexpr int EDGES_MAX = 65536;

// fp16 scratch: [x_src | x_dst | edge_emb], each E*1024
__device__ __align__(16) __half g_xh[(size_t)3 * EDGES_MAX * 1024];
// fp16 weights (gamma folded into up-projection weights), concatenated
__device__ __align__(16) __half g_wh[3145728];
// fp16 RAW down-projection outputs (LN folded into k3)
__device__ __align__(16) __half g_cQh [(size_t)EDGES_MAX * 512];
__device__ __align__(16) __half g_cKVh[(size_t)EDGES_MAX * 512];
// per-row (sum, sumsq) of raw down-proj outputs: rows [0,E) = Q, [E,2E) = KV
__device__ __align__(16) float2 g_stats[(size_t)2 * EDGES_MAX];
// per-output-channel (u, v): u = sum_k gamma_k W_nk, v = sum_k beta_k W_nk
__device__ __align__(16) float2 g_uv[3072];

// weight offsets in g_wh (elements)
static constexpr size_t OFF_WQD  = 0;
static constexpr size_t OFF_WKVD = OFF_WQD  + (size_t)512 * 1024;   //  524288
static constexpr size_t OFF_WQN  = OFF_WKVD + (size_t)512 * 2048;   // 1572864
static constexpr size_t OFF_WKN  = OFF_WQN  + (size_t)2 * 512 * 512;
static constexpr size_t OFF_WV   = OFF_WKN  + (size_t)2 * 512 * 512;

// SMEM geometry
static constexpr int STAGE_B = 32768;
static constexpr int STAGES  = 3;
static constexpr int PIPE_B  = STAGES * STAGE_B;          // 98304
static constexpr int SMEM_K1 = PIPE_B;
static constexpr int SMEM_K3 = PIPE_B + 128 * 16 * 8;

// ============================================================================
// PTX helpers
// ============================================================================
__device__ __forceinline__ uint32_t smem_to_u32(const void* p) {
    uint32_t a;
    asm("{ .reg .u64 t; cvta.to.shared.u64 t, %1; cvt.u32.u64 %0, t; }" : "=r"(a) : "l"(p));
    return a;
}

#define CP_ASYNC16(dst_u32, src_ptr) \
    asm volatile("cp.async.cg.shared.global [%0], [%1], 16;" :: "r"(dst_u32), "l"(src_ptr))
#define CP_COMMIT() asm volatile("cp.async.commit_group;" ::: "memory")
#define CP_WAIT1()  asm volatile("cp.async.wait_group 1;"  ::: "memory")

__device__ __forceinline__ void ldsm_x4(uint32_t* r, uint32_t addr) {
    asm volatile("ldmatrix.sync.aligned.m8n8.x4.shared.b16 {%0,%1,%2,%3}, [%4];"
                 : "=r"(r[0]), "=r"(r[1]), "=r"(r[2]), "=r"(r[3]) : "r"(addr));
}

__device__ __forceinline__ void mma16816(float* d, const uint32_t* a, uint32_t b0, uint32_t b1) {
    asm volatile(
        "mma.sync.aligned.m16n8k16.row.col.f32.f16.f16.f32 "
        "{%0,%1,%2,%3}, {%4,%5,%6,%7}, {%8,%9}, {%0,%1,%2,%3};"
        : "+f"(d[0]), "+f"(d[1]), "+f"(d[2]), "+f"(d[3])
        : "r"(a[0]), "r"(a[1]), "r"(a[2]), "r"(a[3]), "r"(b0), "r"(b1));
}

// ============================================================================
// fp16 tile loader: 128 rows x 64 halves (128B/row), XOR-16B swizzle.
// ============================================================================
__device__ __forceinline__ void load_tile_h(uint32_t dst, const __half* __restrict__ src,
                                            long ld, int tid) {
    #pragma unroll
    for (int i = 0; i < 4; i++) {
        int idx = tid + i * 256;
        int row = idx >> 3, c = idx & 7;
        uint32_t d = dst + (uint32_t)(row * 128 + ((c ^ (row & 7)) << 4));
        CP_ASYNC16(d, src + (size_t)row * ld + c * 8);
    }
}

// ============================================================================
// Core GEMM (unchanged from R13 winner)
// ============================================================================
__device__ void gemm_h(const __half* __restrict__ A0, const __half* __restrict__ A1,
                       int asplit, long lda,
                       const __half* __restrict__ W, long ldw, int nch,
                       void* __restrict__ outp, long ldo, int colbase, int half_out,
                       int rope, const float* __restrict__ lts,
                       const float* __restrict__ t, long e0,
                       float2* __restrict__ stat_out,
                       const float2* __restrict__ stat_in,
                       const float2* __restrict__ uv, int noff)
{
    extern __shared__ char smem[];
    const uint32_t su = smem_to_u32(smem);
    const int tid  = threadIdx.x;
    const int lane = tid & 31;
    const int wid  = tid >> 5, wm = wid & 3, wn = wid >> 2;
    const int l7   = lane & 7, sub = lane >> 3;
    const int khi  = sub >> 1;
    const int rsel = (sub & 1) * 8;

    float2* ropeTab = reinterpret_cast<float2*>(smem + PIPE_B);
    if (rope) {
        for (int idx = tid; idx < 128 * 16; idx += 256) {
            int row = idx >> 4, j = idx & 15;
            float ang = __ldg(t + e0 + row) / expf(__ldg(lts + j));
            float s, c;
            sincosf(ang, &s, &c);
            ropeTab[idx] = make_float2(c, s);
        }
    }

    float acc[2][8][4];
    #pragma unroll
    for (int a = 0; a < 2; a++)
        #pragma unroll
        for (int b = 0; b < 8; b++)
            #pragma unroll
            for (int c = 0; c < 4; c++) acc[a][b][c] = 0.f;

    uint32_t abase[2]; uint32_t a7[2];
    #pragma unroll
    for (int mf = 0; mf < 2; mf++) {
        int r = wm * 32 + mf * 16 + rsel + l7;
        a7[mf] = (uint32_t)(r & 7);
        abase[mf] = (uint32_t)(r * 128);
    }
    uint32_t bbase[4]; uint32_t b7[4];
    #pragma unroll
    for (int np = 0; np < 4; np++) {
        int r = wn * 64 + np * 16 + rsel + l7;
        b7[np] = (uint32_t)(r & 7);
        bbase[np] = (uint32_t)(r * 128);
    }

    auto a_src = [&](int c) -> const __half* {
        return (c < asplit) ? (A0 + (size_t)c * 64) : (A1 + (size_t)(c - asplit) * 64);
    };

    load_tile_h(su, a_src(0), lda, tid);
    load_tile_h(su + 16384, W, ldw, tid);
    CP_COMMIT();
    if (nch > 1) {
        load_tile_h(su + STAGE_B, a_src(1), lda, tid);
        load_tile_h(su + STAGE_B + 16384, W + 64, ldw, tid);
    }
    CP_COMMIT();

    for (int c = 0; c < nch; c++) {
        const int st = c % STAGES;
        CP_WAIT1();
        __syncthreads();
        if (c + 2 < nch) {
            const int s2 = (c + 2) % STAGES;
            load_tile_h(su + (uint32_t)(s2 * STAGE_B), a_src(c + 2), lda, tid);
            load_tile_h(su + (uint32_t)(s2 * STAGE_B + 16384), W + (size_t)(c + 2) * 64, ldw, tid);
        }
        CP_COMMIT();

        const uint32_t As = su + st * STAGE_B;
        const uint32_t Bs = As + 16384;
        #pragma unroll
        for (int ks = 0; ks < 4; ks++) {
            const uint32_t kb = (uint32_t)(ks * 2 + khi);
            uint32_t af[2][4];
            #pragma unroll
            for (int mf = 0; mf < 2; mf++)
                ldsm_x4(af[mf], As + abase[mf] + ((kb ^ a7[mf]) << 4));
            uint32_t bq[4][4];
            #pragma unroll
            for (int np = 0; np < 4; np++)
                ldsm_x4(bq[np], Bs + bbase[np] + ((kb ^ b7[np]) << 4));
            #pragma unroll
            for (int mf = 0; mf < 2; mf++)
                #pragma unroll
                for (int np = 0; np < 4; np++) {
                    mma16816(acc[mf][np * 2 + 0], af[mf], bq[np][0], bq[np][2]);
                    mma16816(acc[mf][np * 2 + 1], af[mf], bq[np][1], bq[np][3]);
                }
        }
    }

    const int gid = lane >> 2, tig = lane & 3;

    if (half_out) {
        #pragma unroll
        for (int mf = 0; mf < 2; mf++) {
            #pragma unroll
            for (int rr = 0; rr < 2; rr++) {
                const int row = wm * 32 + mf * 16 + rr * 8 + gid;
                const size_t rb = (size_t)(e0 + row) * ldo + colbase;
                float s1 = 0.f, s2 = 0.f;
                #pragma unroll
                for (int nf = 0; nf < 8; nf++) {
                    const int col = wn * 64 + nf * 8 + tig * 2;
                    float x0 = acc[mf][nf][rr * 2 + 0];
                    float x1 = acc[mf][nf][rr * 2 + 1];
                    s1 += x0 + x1;
                    s2 += x0 * x0 + x1 * x1;
                    *reinterpret_cast<__half2*>(reinterpret_cast<__half*>(outp) + rb + col) =
                        __floats2half2_rn(x0, x1);
                }
                s1 += __shfl_xor_sync(0xFFFFFFFFu, s1, 1);
                s2 += __shfl_xor_sync(0xFFFFFFFFu, s2, 1);
                s1 += __shfl_xor_sync(0xFFFFFFFFu, s1, 2);
                s2 += __shfl_xor_sync(0xFFFFFFFFu, s2, 2);
                if (tig == 0) {
                    atomicAdd(&stat_out[row].x, s1);
                    atomicAdd(&stat_out[row].y, s2);
                }
            }
        }
    } else {
        float4 uvf[8];
        #pragma unroll
        for (int nf = 0; nf < 8; nf++) {
            const int col = wn * 64 + nf * 8 + tig * 2;
            uvf[nf] = *reinterpret_cast<const float4*>(&uv[noff + col]);
        }
        #pragma unroll
        for (int mf = 0; mf < 2; mf++) {
            #pragma unroll
            for (int rr = 0; rr < 2; rr++) {
                const int row = wm * 32 + mf * 16 + rr * 8 + gid;
                const size_t rb = (size_t)(e0 + row) * ldo + colbase;
                float2 st = stat_in[row];
                float mu   = st.x * (1.f / 512.f);
                float var  = st.y * (1.f / 512.f) - mu * mu;
                float rstd = rsqrtf(var + 1e-5f);
                float cm   = -rstd * mu;
                #pragma unroll
                for (int nf = 0; nf < 8; nf++) {
                    const int col = wn * 64 + nf * 8 + tig * 2;
                    float x0 = acc[mf][nf][rr * 2 + 0];
                    float x1 = acc[mf][nf][rr * 2 + 1];
                    x0 = fmaf(rstd, x0, fmaf(cm, uvf[nf].x, uvf[nf].y));
                    x1 = fmaf(rstd, x1, fmaf(cm, uvf[nf].z, uvf[nf].w));
                    if (rope) {
                        float2 cs = ropeTab[row * 16 + ((col & 31) >> 1)];
                        float y0 = x0 * cs.x - x1 * cs.y;
                        float y1 = x0 * cs.y + x1 * cs.x;
                        x0 = y0; x1 = y1;
                    }
                    __stcs(reinterpret_cast<float2*>(reinterpret_cast<float*>(outp) + rb + col),
                           make_float2(x0, x1));
                }
            }
        }
    }
}

// ============================================================================
// Convert helper: 16 floats -> 16 halves (optionally gamma-folded)
// ============================================================================
__device__ __forceinline__ void cvt16(const float* __restrict__ s, __half* __restrict__ d,
                                      const float* __restrict__ gam, int gcol) {
    float4 v[4];
    #pragma unroll
    for (int q = 0; q < 4; q++) v[q] = *reinterpret_cast<const float4*>(s + q * 4);
    if (gam) {
        #pragma unroll
        for (int q = 0; q < 4; q++) {
            float4 gq = *reinterpret_cast<const float4*>(gam + gcol + q * 4);
            v[q].x *= gq.x; v[q].y *= gq.y; v[q].z *= gq.z; v[q].w *= gq.w;
        }
    }
    __half2 h[8];
    #pragma unroll
    for (int q = 0; q < 4; q++) {
        h[q * 2 + 0] = __floats2half2_rn(v[q].x, v[q].y);
        h[q * 2 + 1] = __floats2half2_rn(v[q].z, v[q].w);
    }
    *reinterpret_cast<uint4*>(d)     = reinterpret_cast<uint4*>(h)[0];
    *reinterpret_cast<uint4*>(d + 8) = reinterpret_cast<uint4*>(h)[1];
}

// ============================================================================
// cvt_A: x_src + Wqd + stats-zero  (everything k1Q needs)
// ============================================================================
__global__ void __launch_bounds__(256)
cvt_a(const float* __restrict__ x_src, const float* __restrict__ Wqd, long EX)
{
    const unsigned zb = (unsigned)(EX >> 18);              // E/256 zero blocks
    const unsigned zbase = gridDim.x - zb;
    if (blockIdx.x >= zbase) {
        size_t idx = (size_t)(blockIdx.x - zbase) * 256 + threadIdx.x;
        reinterpret_cast<float4*>(g_stats)[idx] = make_float4(0.f, 0.f, 0.f, 0.f);
        return;
    }
    size_t i = ((size_t)blockIdx.x * 256 + threadIdx.x) * 16;
    if (i < (size_t)EX) cvt16(x_src + i, g_xh + i, nullptr, 0);
    else {
        size_t j = i - (size_t)EX;
        cvt16(Wqd + j, g_wh + OFF_WQD + j, nullptr, 0);
    }
}

// ============================================================================
// cvt_B: x_dst, edge, Wkvd, gamma-folded up-weights, uv  (k1KV + k3 inputs)
// ============================================================================
static constexpr unsigned UV_BLOCKS = 384;

__global__ void __launch_bounds__(256)
cvt_b(const float* __restrict__ x_dst, const float* __restrict__ edge,
      const float* __restrict__ Wkvd,
      const float* __restrict__ Wqn, const float* __restrict__ Wqr,
      const float* __restrict__ Wkn, const float* __restrict__ Wkr,
      const float* __restrict__ Wv,
      const float* __restrict__ qg, const float* __restrict__ qb,
      const float* __restrict__ kvg, const float* __restrict__ kvb, long EX)
{
    const unsigned uvbase = gridDim.x - UV_BLOCKS;
    if (blockIdx.x >= uvbase) {
        const int n = (int)((blockIdx.x - uvbase) * 8 + (threadIdx.x >> 5));
        const int lane = threadIdx.x & 31;
        const float* wrow;
        const float *g, *b;
        if      (n < 512)  { wrow = Wqn + (size_t)n * 512;          g = qg;  b = qb;  }
        else if (n < 1024) { wrow = Wqr + (size_t)(n - 512) * 512;  g = qg;  b = qb;  }
        else if (n < 1536) { wrow = Wkn + (size_t)(n - 1024) * 512; g = kvg; b = kvb; }
        else if (n < 2048) { wrow = Wkr + (size_t)(n - 1536) * 512; g = kvg; b = kvb; }
        else               { wrow = Wv  + (size_t)(n - 2048) * 512; g = kvg; b = kvb; }
        float u = 0.f, v = 0.f;
        #pragma unroll
        for (int k = lane; k < 512; k += 32) {
            float w = wrow[k];
            u += w * g[k];
            v += w * b[k];
        }
        #pragma unroll
        for (int o = 16; o > 0; o >>= 1) {
            u += __shfl_xor_sync(0xFFFFFFFFu, u, o);
            v += __shfl_xor_sync(0xFFFFFFFFu, v, o);
        }
        if (lane == 0) g_uv[n] = make_float2(u, v);
        return;
    }

    size_t i = ((size_t)blockIdx.x * 256 + threadIdx.x) * 16;
    const size_t AX = (size_t)EX;
    if (i < 2 * AX) {
        const float* s = (i < AX) ? (x_dst + i) : (edge + (i - AX));
        cvt16(s, g_xh + AX + i, nullptr, 0);
    } else {
        size_t j = i - 2 * AX;
        if (j < (size_t)1048576) {
            cvt16(Wkvd + j, g_wh + OFF_WKVD + j, nullptr, 0);
        } else {
            size_t jj = j - 1048576;   // [0, 1572864) over up-weights
            const float* srcs[6] = { Wqn, Wqr, Wkn, Wkr, Wv, Wv + (size_t)262144 };
            int r = (int)(jj >> 18);
            const float* s = srcs[r] + (jj & 0x3FFFF);
            const float* gam = (jj < (size_t)524288) ? qg : kvg;
            cvt16(s, g_wh + OFF_WQN + jj, gam, (int)(jj & 511));
        }
    }
}

// ============================================================================
// K1-Q and K1-KV (split for stream overlap); bodies identical to R13.
// ============================================================================
__global__ void __launch_bounds__(256, 2)
mla_k1q(int E)
{
    const int seg = blockIdx.x & 3, mt = blockIdx.x >> 2;
    const long e0 = (long)mt * 128;
    gemm_h(g_xh + e0 * 1024, nullptr, 1 << 30, 1024,
           g_wh + OFF_WQD + (size_t)seg * 128 * 1024, 1024, 16,
           g_cQh, 512, seg * 128, 1, 0, nullptr, nullptr, e0,
           g_stats + e0, nullptr, nullptr, 0);
}

__global__ void __launch_bounds__(256, 2)
mla_k1kv(int E)
{
    const int seg = blockIdx.x & 3, mt = blockIdx.x >> 2;
    const long e0 = (long)mt * 128;
    const __half* xd = g_xh + (size_t)E * 1024;
    const __half* xe = g_xh + (size_t)2 * E * 1024;
    gemm_h(xd + e0 * 1024, xe + e0 * 1024, 16, 1024,
           g_wh + OFF_WKVD + (size_t)seg * 128 * 2048, 2048, 32,
           g_cKVh, 512, seg * 128, 1, 0, nullptr, nullptr, e0,
           g_stats + E + e0, nullptr, nullptr, 0);
}

// ============================================================================
// K3: up-projections on RAW scratch + fused LN affine + RoPE.
// ============================================================================
__global__ void __launch_bounds__(256, 2)
mla_k3(const float* __restrict__ t,
       const float* __restrict__ qlts, const float* __restrict__ klts,
       float* __restrict__ out, int E)
{
    const int y = blockIdx.x;
    const long e0 = (long)blockIdx.y * 128;
    const long S = (long)E * 512;

    const __half* A;
    const __half* W;
    float* o;
    long ldo;
    int colbase, rope = 0, noff;
    const float* lts = nullptr;
    const float2* stat;

    if (y < 16) {
        const int seg = y >> 2, nt = y & 3;
        A = ((seg < 2) ? g_cQh : g_cKVh) + e0 * 512;
        stat = g_stats + ((seg < 2) ? 0 : E) + e0;
        W = g_wh + OFF_WQN + (size_t)seg * 262144 + (size_t)nt * 128 * 512;
        o = out + (long)seg * S;
        ldo = 512;
        colbase = nt * 128;
        noff = seg * 512 + colbase;
        if (seg == 1) { rope = 1; lts = qlts; }
        if (seg == 3) { rope = 1; lts = klts; }
    } else {
        const int nt = y - 16;
        A = g_cKVh + e0 * 512;
        stat = g_stats + E + e0;
        W = g_wh + OFF_WV + (size_t)nt * 128 * 512;
        o = out + 4 * S;
        ldo = 1024;
        colbase = nt * 128;
        noff = 2048 + colbase;
    }
    gemm_h(A, nullptr, 1 << 30, 512, W, 512, 8, o, ldo, colbase, 0, rope, lts, t, e0,
           nullptr, stat, g_uv, noff);
}

// ============================================================================
// Launch. Fork/join: cvt_a -> {k1q || cvt_b(s1)} -> k1kv -> k3.
// ============================================================================
extern "C" void kernel_launch(void* const* d_in, const int* in_sizes, int n_in,
                              void* d_out, int out_size) {
    const float* x_src = (const float*)d_in[0];
    const float* x_dst = (const float*)d_in[1];
    const float* edge  = (const float*)d_in[2];
    const float* t     = (const float*)d_in[3];
    const float* Wqd   = (const float*)d_in[4];
    const float* qg    = (const float*)d_in[5];
    const float* qb    = (const float*)d_in[6];
    const float* Wqn   = (const float*)d_in[7];
    const float* Wqr   = (const float*)d_in[8];
    const float* Wkvd  = (const float*)d_in[9];
    const float* kvg   = (const float*)d_in[10];
    const float* kvb   = (const float*)d_in[11];
    const float* Wkn   = (const float*)d_in[12];
    const float* Wkr   = (const float*)d_in[13];
    const float* Wv    = (const float*)d_in[14];
    const float* qlts  = (const float*)d_in[15];
    const float* klts  = (const float*)d_in[16];
    float* out = (float*)d_out;

    static bool init_done = false;
    static bool use_streams = false;
    static cudaStream_t s1;
    static cudaEvent_t evA, evB;
    if (!init_done) {
        cudaFuncSetAttribute(mla_k1q,  cudaFuncAttributeMaxDynamicSharedMemorySize, SMEM_K1);
        cudaFuncSetAttribute(mla_k1kv, cudaFuncAttributeMaxDynamicSharedMemorySize, SMEM_K1);
        cudaFuncSetAttribute(mla_k3,   cudaFuncAttributeMaxDynamicSharedMemorySize, SMEM_K3);
        use_streams =
            (cudaStreamCreateWithFlags(&s1, cudaStreamNonBlocking) == cudaSuccess) &&
            (cudaEventCreateWithFlags(&evA, cudaEventDisableTiming) == cudaSuccess) &&
            (cudaEventCreateWithFlags(&evB, cudaEventDisableTiming) == cudaSuccess);
        init_done = true;
    }

    const int E = in_sizes[3];
    const long EX = (long)E * 1024;

    const unsigned gA = (unsigned)((EX + 524288) / 4096) + (unsigned)(E / 256);
    const unsigned gB = (unsigned)((2 * EX + 1048576 + 1572864) / 4096) + UV_BLOCKS;

    cvt_a<<<gA, 256>>>(x_src, Wqd, EX);

    if (use_streams) {
        cudaEventRecord(evA, 0);
        cudaStreamWaitEvent(s1, evA, 0);
        cvt_b<<<gB, 256, 0, s1>>>(x_dst, edge, Wkvd, Wqn, Wqr, Wkn, Wkr, Wv,
                                  qg, qb, kvg, kvb, EX);
        cudaEventRecord(evB, s1);
        mla_k1q<<<4 * (E / 128), 256, SMEM_K1>>>(E);       // overlaps cvt_b
        cudaStreamWaitEvent(0, evB, 0);
    } else {
        cvt_b<<<gB, 256>>>(x_dst, edge, Wkvd, Wqn, Wqr, Wkn, Wkr, Wv,
                           qg, qb, kvg, kvb, EX);
        mla_k1q<<<4 * (E / 128), 256, SMEM_K1>>>(E);
    }

    mla_k1kv<<<4 * (E / 128), 256, SMEM_K1>>>(E);
    mla_k3<<<dim3(24, E / 128), 256, SMEM_K3>>>(t, qlts, klts, out, E);
}

// round 15
// speedup vs baseline: 1.0017x; 1.0017x over previous
#include <cuda_runtime.h>
#include <cuda_fp16.h>
#include <cstdint>

// ============================================================================
// Problem constants
// ============================================================================
static constexpr int EDGES_MAX = 65536;

// fp16 scratch: [x_src | x_dst | edge_emb], each E*1024
__device__ __align__(16) __half g_xh[(size_t)3 * EDGES_MAX * 1024];
// fp16 weights (gamma folded into up-projection weights), concatenated
__device__ __align__(16) __half g_wh[3145728];
// fp16 RAW down-projection outputs (LN folded into k3)
__device__ __align__(16) __half g_cQh [(size_t)EDGES_MAX * 512];
__device__ __align__(16) __half g_cKVh[(size_t)EDGES_MAX * 512];
// per-row (sum, sumsq) of raw down-proj outputs: rows [0,E) = Q, [E,2E) = KV
__device__ __align__(16) float2 g_stats[(size_t)2 * EDGES_MAX];
// per-output-channel (u, v): u = sum_k gamma_k W_nk, v = sum_k beta_k W_nk
// layout: [Wqn 512 | Wqr 512 | Wkn 512 | Wkr 512 | Wv 1024]
__device__ __align__(16) float2 g_uv[3072];

// weight offsets in g_wh (elements)
static constexpr size_t OFF_WQD  = 0;
static constexpr size_t OFF_WKVD = OFF_WQD  + (size_t)512 * 1024;   //  524288
static constexpr size_t OFF_WQN  = OFF_WKVD + (size_t)512 * 2048;   // 1572864
static constexpr size_t OFF_WQR  = OFF_WQN  + (size_t)512 * 512;
static constexpr size_t OFF_WKN  = OFF_WQR  + (size_t)512 * 512;
static constexpr size_t OFF_WKR  = OFF_WKN  + (size_t)512 * 512;
static constexpr size_t OFF_WV   = OFF_WKR  + (size_t)512 * 512;
static constexpr size_t OFF_END  = OFF_WV   + (size_t)1024 * 512;   // 3145728

// SMEM: per stage A[128x64 fp16]=16KB + B[128x64 fp16]=16KB, 3 stages.
static constexpr int STAGE_B = 32768;
static constexpr int STAGES  = 3;
static constexpr int PIPE_B  = STAGES * STAGE_B;          // 98304
static constexpr int SMEM_K1 = PIPE_B;
static constexpr int SMEM_K3 = PIPE_B + 128 * 16 * 8;     // + rope float2 table

// ============================================================================
// PTX helpers
// ============================================================================
__device__ __forceinline__ uint32_t smem_to_u32(const void* p) {
    uint32_t a;
    asm("{ .reg .u64 t; cvta.to.shared.u64 t, %1; cvt.u32.u64 %0, t; }" : "=r"(a) : "l"(p));
    return a;
}

#define CP_ASYNC16(dst_u32, src_ptr) \
    asm volatile("cp.async.cg.shared.global [%0], [%1], 16;" :: "r"(dst_u32), "l"(src_ptr))
#define CP_COMMIT() asm volatile("cp.async.commit_group;" ::: "memory")
#define CP_WAIT1()  asm volatile("cp.async.wait_group 1;"  ::: "memory")

__device__ __forceinline__ void ldsm_x4(uint32_t* r, uint32_t addr) {
    asm volatile("ldmatrix.sync.aligned.m8n8.x4.shared.b16 {%0,%1,%2,%3}, [%4];"
                 : "=r"(r[0]), "=r"(r[1]), "=r"(r[2]), "=r"(r[3]) : "r"(addr));
}

__device__ __forceinline__ void mma16816(float* d, const uint32_t* a, uint32_t b0, uint32_t b1) {
    asm volatile(
        "mma.sync.aligned.m16n8k16.row.col.f32.f16.f16.f32 "
        "{%0,%1,%2,%3}, {%4,%5,%6,%7}, {%8,%9}, {%0,%1,%2,%3};"
        : "+f"(d[0]), "+f"(d[1]), "+f"(d[2]), "+f"(d[3])
        : "r"(a[0]), "r"(a[1]), "r"(a[2]), "r"(a[3]), "r"(b0), "r"(b1));
}

// ============================================================================
// fp16 tile loader: 128 rows x 64 halves (128B/row), XOR-16B swizzle.
// ============================================================================
__device__ __forceinline__ void load_tile_h(uint32_t dst, const __half* __restrict__ src,
                                            long ld, int tid) {
    #pragma unroll
    for (int i = 0; i < 4; i++) {
        int idx = tid + i * 256;
        int row = idx >> 3, c = idx & 7;
        uint32_t d = dst + (uint32_t)(row * 128 + ((c ^ (row & 7)) << 4));
        CP_ASYNC16(d, src + (size_t)row * ld + c * 8);
    }
}

// ============================================================================
// Core: C[128,128] = A[128,K] * W[128,K]^T (fp16 in, fp32 accum)
// 8 warps 4(M) x 2(N), warp tile 32x64, K chunks of 64. 3-deep cp.async pipe.
// half_out: write raw fp16 + emit per-row (sum,sumsq) partials to stat_out.
// else:     apply per-row LN affine (stat_in + uv at noff) then optional RoPE,
//           streaming fp32 store. Stat loads batched (MLP=4) at epilogue top.
// ============================================================================
__device__ void gemm_h(const __half* __restrict__ A0, const __half* __restrict__ A1,
                       int asplit, long lda,
                       const __half* __restrict__ W, long ldw, int nch,
                       void* __restrict__ outp, long ldo, int colbase, int half_out,
                       int rope, const float* __restrict__ lts,
                       const float* __restrict__ t, long e0,
                       float2* __restrict__ stat_out,          // prebased +e0 (k1)
                       const float2* __restrict__ stat_in,     // prebased +e0 (k3)
                       const float2* __restrict__ uv, int noff)
{
    extern __shared__ char smem[];
    const uint32_t su = smem_to_u32(smem);
    const int tid  = threadIdx.x;
    const int lane = tid & 31;
    const int wid  = tid >> 5, wm = wid & 3, wn = wid >> 2;
    const int l7   = lane & 7, sub = lane >> 3;
    const int khi  = sub >> 1;
    const int rsel = (sub & 1) * 8;

    float2* ropeTab = reinterpret_cast<float2*>(smem + PIPE_B);
    if (rope) {
        for (int idx = tid; idx < 128 * 16; idx += 256) {
            int row = idx >> 4, j = idx & 15;
            float ang = __ldg(t + e0 + row) / expf(__ldg(lts + j));
            float s, c;
            sincosf(ang, &s, &c);
            ropeTab[idx] = make_float2(c, s);
        }
    }

    float acc[2][8][4];
    #pragma unroll
    for (int a = 0; a < 2; a++)
        #pragma unroll
        for (int b = 0; b < 8; b++)
            #pragma unroll
            for (int c = 0; c < 4; c++) acc[a][b][c] = 0.f;

    uint32_t abase[2]; uint32_t a7[2];
    #pragma unroll
    for (int mf = 0; mf < 2; mf++) {
        int r = wm * 32 + mf * 16 + rsel + l7;
        a7[mf] = (uint32_t)(r & 7);
        abase[mf] = (uint32_t)(r * 128);
    }
    uint32_t bbase[4]; uint32_t b7[4];
    #pragma unroll
    for (int np = 0; np < 4; np++) {
        int r = wn * 64 + np * 16 + rsel + l7;
        b7[np] = (uint32_t)(r & 7);
        bbase[np] = (uint32_t)(r * 128);
    }

    auto a_src = [&](int c) -> const __half* {
        return (c < asplit) ? (A0 + (size_t)c * 64) : (A1 + (size_t)(c - asplit) * 64);
    };

    load_tile_h(su, a_src(0), lda, tid);
    load_tile_h(su + 16384, W, ldw, tid);
    CP_COMMIT();
    if (nch > 1) {
        load_tile_h(su + STAGE_B, a_src(1), lda, tid);
        load_tile_h(su + STAGE_B + 16384, W + 64, ldw, tid);
    }
    CP_COMMIT();

    for (int c = 0; c < nch; c++) {
        const int st = c % STAGES;
        CP_WAIT1();
        __syncthreads();
        if (c + 2 < nch) {
            const int s2 = (c + 2) % STAGES;
            load_tile_h(su + (uint32_t)(s2 * STAGE_B), a_src(c + 2), lda, tid);
            load_tile_h(su + (uint32_t)(s2 * STAGE_B + 16384), W + (size_t)(c + 2) * 64, ldw, tid);
        }
        CP_COMMIT();

        const uint32_t As = su + st * STAGE_B;
        const uint32_t Bs = As + 16384;
        #pragma unroll
        for (int ks = 0; ks < 4; ks++) {
            const uint32_t kb = (uint32_t)(ks * 2 + khi);
            uint32_t af[2][4];
            #pragma unroll
            for (int mf = 0; mf < 2; mf++)
                ldsm_x4(af[mf], As + abase[mf] + ((kb ^ a7[mf]) << 4));
            uint32_t bq[4][4];
            #pragma unroll
            for (int np = 0; np < 4; np++)
                ldsm_x4(bq[np], Bs + bbase[np] + ((kb ^ b7[np]) << 4));
            #pragma unroll
            for (int mf = 0; mf < 2; mf++)
                #pragma unroll
                for (int np = 0; np < 4; np++) {
                    mma16816(acc[mf][np * 2 + 0], af[mf], bq[np][0], bq[np][2]);
                    mma16816(acc[mf][np * 2 + 1], af[mf], bq[np][1], bq[np][3]);
                }
        }
    }

    const int gid = lane >> 2, tig = lane & 3;

    if (half_out) {
        // raw fp16 store + per-row (sum, sumsq) partial emission
        #pragma unroll
        for (int mf = 0; mf < 2; mf++) {
            #pragma unroll
            for (int rr = 0; rr < 2; rr++) {
                const int row = wm * 32 + mf * 16 + rr * 8 + gid;
                const size_t rb = (size_t)(e0 + row) * ldo + colbase;
                float s1 = 0.f, s2 = 0.f;
                #pragma unroll
                for (int nf = 0; nf < 8; nf++) {
                    const int col = wn * 64 + nf * 8 + tig * 2;
                    float x0 = acc[mf][nf][rr * 2 + 0];
                    float x1 = acc[mf][nf][rr * 2 + 1];
                    s1 += x0 + x1;
                    s2 += x0 * x0 + x1 * x1;
                    *reinterpret_cast<__half2*>(reinterpret_cast<__half*>(outp) + rb + col) =
                        __floats2half2_rn(x0, x1);
                }
                s1 += __shfl_xor_sync(0xFFFFFFFFu, s1, 1);
                s2 += __shfl_xor_sync(0xFFFFFFFFu, s2, 1);
                s1 += __shfl_xor_sync(0xFFFFFFFFu, s1, 2);
                s2 += __shfl_xor_sync(0xFFFFFFFFu, s2, 2);
                if (tig == 0) {
                    atomicAdd(&stat_out[row].x, s1);
                    atomicAdd(&stat_out[row].y, s2);
                }
            }
        }
    } else {
        // Batch ALL global loads first (4 stat LDG.64 + 8 uv LDG.128, MLP high),
        // then compute. Removes serialized per-iteration load latency at tail.
        float2 st4[2][2];
        #pragma unroll
        for (int mf = 0; mf < 2; mf++)
            #pragma unroll
            for (int rr = 0; rr < 2; rr++)
                st4[mf][rr] = stat_in[wm * 32 + mf * 16 + rr * 8 + gid];

        float4 uvf[8];
        #pragma unroll
        for (int nf = 0; nf < 8; nf++) {
            const int col = wn * 64 + nf * 8 + tig * 2;
            uvf[nf] = *reinterpret_cast<const float4*>(&uv[noff + col]);
        }

        float rstd4[2][2], cm4[2][2];
        #pragma unroll
        for (int mf = 0; mf < 2; mf++)
            #pragma unroll
            for (int rr = 0; rr < 2; rr++) {
                float mu   = st4[mf][rr].x * (1.f / 512.f);
                float var  = st4[mf][rr].y * (1.f / 512.f) - mu * mu;
                float rstd = rsqrtf(var + 1e-5f);
                rstd4[mf][rr] = rstd;
                cm4[mf][rr]   = -rstd * mu;
            }

        #pragma unroll
        for (int mf = 0; mf < 2; mf++) {
            #pragma unroll
            for (int rr = 0; rr < 2; rr++) {
                const int row = wm * 32 + mf * 16 + rr * 8 + gid;
                const size_t rb = (size_t)(e0 + row) * ldo + colbase;
                const float rstd = rstd4[mf][rr];
                const float cm   = cm4[mf][rr];
                #pragma unroll
                for (int nf = 0; nf < 8; nf++) {
                    const int col = wn * 64 + nf * 8 + tig * 2;
                    float x0 = acc[mf][nf][rr * 2 + 0];
                    float x1 = acc[mf][nf][rr * 2 + 1];
                    x0 = fmaf(rstd, x0, fmaf(cm, uvf[nf].x, uvf[nf].y));
                    x1 = fmaf(rstd, x1, fmaf(cm, uvf[nf].z, uvf[nf].w));
                    if (rope) {
                        float2 cs = ropeTab[row * 16 + ((col & 31) >> 1)];
                        float y0 = x0 * cs.x - x1 * cs.y;
                        float y1 = x0 * cs.y + x1 * cs.x;
                        x0 = y0; x1 = y1;
                    }
                    __stcs(reinterpret_cast<float2*>(reinterpret_cast<float*>(outp) + rb + col),
                           make_float2(x0, x1));
                }
            }
        }
    }
}

// ============================================================================
// Prepass (ONE launch): grid = [convert blocks | stats-zero blocks | uv blocks]
// ============================================================================
static constexpr unsigned UV_BLOCKS = 384;

__global__ void __launch_bounds__(256)
cvt_all(const float* __restrict__ x_src, const float* __restrict__ x_dst,
        const float* __restrict__ edge,
        const float* __restrict__ Wqd, const float* __restrict__ Wkvd,
        const float* __restrict__ Wqn, const float* __restrict__ Wqr,
        const float* __restrict__ Wkn, const float* __restrict__ Wkr,
        const float* __restrict__ Wv,
        const float* __restrict__ qg, const float* __restrict__ qb,
        const float* __restrict__ kvg, const float* __restrict__ kvb, long EX)
{
    const unsigned zb = (unsigned)(EX >> 18);              // E/256 zero blocks
    const unsigned zbase  = gridDim.x - UV_BLOCKS - zb;    // first zero block
    const unsigned uvbase = gridDim.x - UV_BLOCKS;         // first uv block

    if (blockIdx.x >= uvbase) {
        const int n = (int)((blockIdx.x - uvbase) * 8 + (threadIdx.x >> 5));
        const int lane = threadIdx.x & 31;
        const float* wrow;
        const float *g, *b;
        if      (n < 512)  { wrow = Wqn + (size_t)n * 512;          g = qg;  b = qb;  }
        else if (n < 1024) { wrow = Wqr + (size_t)(n - 512) * 512;  g = qg;  b = qb;  }
        else if (n < 1536) { wrow = Wkn + (size_t)(n - 1024) * 512; g = kvg; b = kvb; }
        else if (n < 2048) { wrow = Wkr + (size_t)(n - 1536) * 512; g = kvg; b = kvb; }
        else               { wrow = Wv  + (size_t)(n - 2048) * 512; g = kvg; b = kvb; }
        float u = 0.f, v = 0.f;
        #pragma unroll
        for (int k = lane; k < 512; k += 32) {
            float w = wrow[k];
            u += w * g[k];
            v += w * b[k];
        }
        #pragma unroll
        for (int o = 16; o > 0; o >>= 1) {
            u += __shfl_xor_sync(0xFFFFFFFFu, u, o);
            v += __shfl_xor_sync(0xFFFFFFFFu, v, o);
        }
        if (lane == 0) g_uv[n] = make_float2(u, v);
        return;
    }
    if (blockIdx.x >= zbase) {
        size_t idx = (size_t)(blockIdx.x - zbase) * 256 + threadIdx.x;
        reinterpret_cast<float4*>(g_stats)[idx] = make_float4(0.f, 0.f, 0.f, 0.f);
        return;
    }

    // ---- convert: 16 floats per thread ----
    size_t i = ((size_t)blockIdx.x * 256 + threadIdx.x) * 16;
    const float* s;
    __half* d;
    const size_t AX = (size_t)EX;
    bool fold = false;
    const float* gam = nullptr;
    int gcol = 0;
    if (i < 3 * AX) {
        size_t r = i / AX;
        s = ((r == 0) ? x_src : (r == 1) ? x_dst : edge) + (i - r * AX);
        d = g_xh + i;
    } else {
        size_t j = i - 3 * AX;
        const size_t bounds[8] = { OFF_WQD, OFF_WKVD, OFF_WQN, OFF_WQR,
                                   OFF_WKN, OFF_WKR, OFF_WV, OFF_END };
        const float* srcs[7] = { Wqd, Wkvd, Wqn, Wqr, Wkn, Wkr, Wv };
        int r = 0;
        #pragma unroll
        for (int k = 1; k < 7; k++) r += (j >= bounds[k]);
        s = srcs[r] + (j - bounds[r]);
        d = g_wh + j;
        if (j >= OFF_WQN) {
            fold = true;
            gam = (j < OFF_WKN) ? qg : kvg;
            gcol = (int)(j & 511);
        }
    }
    float4 v[4];
    #pragma unroll
    for (int q = 0; q < 4; q++) v[q] = *reinterpret_cast<const float4*>(s + q * 4);
    if (fold) {
        #pragma unroll
        for (int q = 0; q < 4; q++) {
            float4 gq = *reinterpret_cast<const float4*>(gam + gcol + q * 4);
            v[q].x *= gq.x; v[q].y *= gq.y; v[q].z *= gq.z; v[q].w *= gq.w;
        }
    }
    __half2 h[8];
    #pragma unroll
    for (int q = 0; q < 4; q++) {
        h[q * 2 + 0] = __floats2half2_rn(v[q].x, v[q].y);
        h[q * 2 + 1] = __floats2half2_rn(v[q].z, v[q].w);
    }
    *reinterpret_cast<uint4*>(d)     = reinterpret_cast<uint4*>(h)[0];
    *reinterpret_cast<uint4*>(d + 8) = reinterpret_cast<uint4*>(h)[1];
}

// ============================================================================
// K1: down-projections (raw out + stats). KV CTAs first (long), then Q.
// ============================================================================
__global__ void __launch_bounds__(256, 2)
mla_k1(int E)
{
    const int kvctas = 4 * (E / 128);
    const int id = blockIdx.x;
    const __half* xs = g_xh;
    const __half* xd = g_xh + (size_t)E * 1024;
    const __half* xe = g_xh + (size_t)2 * E * 1024;
    if (id < kvctas) {
        const int seg = id & 3, mt = id >> 2;
        const long e0 = (long)mt * 128;
        gemm_h(xd + e0 * 1024, xe + e0 * 1024, 16, 1024,
               g_wh + OFF_WKVD + (size_t)seg * 128 * 2048, 2048, 32,
               g_cKVh, 512, seg * 128, 1, 0, nullptr, nullptr, e0,
               g_stats + E + e0, nullptr, nullptr, 0);
    } else {
        const int j = id - kvctas;
        const int seg = j & 3, mt = j >> 2;
        const long e0 = (long)mt * 128;
        gemm_h(xs + e0 * 1024, nullptr, 1 << 30, 1024,
               g_wh + OFF_WQD + (size_t)seg * 128 * 1024, 1024, 16,
               g_cQh, 512, seg * 128, 1, 0, nullptr, nullptr, e0,
               g_stats + e0, nullptr, nullptr, 0);
    }
}

// ============================================================================
// K3: up-projections on RAW scratch + fused LN affine + RoPE.
// grid (24, tiles): x = segment (fast).
// ============================================================================
__global__ void __launch_bounds__(256, 2)
mla_k3(const float* __restrict__ t,
       const float* __restrict__ qlts, const float* __restrict__ klts,
       float* __restrict__ out, int E)
{
    const int y = blockIdx.x;
    const long e0 = (long)blockIdx.y * 128;
    const long S = (long)E * 512;

    const __half* A;
    const __half* W;
    float* o;
    long ldo;
    int colbase, rope = 0, noff;
    const float* lts = nullptr;
    const float2* stat;

    if (y < 16) {
        const int seg = y >> 2, nt = y & 3;
        A = ((seg < 2) ? g_cQh : g_cKVh) + e0 * 512;
        stat = g_stats + ((seg < 2) ? 0 : E) + e0;
        const size_t offs[4] = { OFF_WQN, OFF_WQR, OFF_WKN, OFF_WKR };
        W = g_wh + offs[seg] + (size_t)nt * 128 * 512;
        o = out + (long)seg * S;
        ldo = 512;
        colbase = nt * 128;
        noff = seg * 512 + colbase;
        if (seg == 1) { rope = 1; lts = qlts; }
        if (seg == 3) { rope = 1; lts = klts; }
    } else {
        const int nt = y - 16;
        A = g_cKVh + e0 * 512;
        stat = g_stats + E + e0;
        W = g_wh + OFF_WV + (size_t)nt * 128 * 512;
        o = out + 4 * S;
        ldo = 1024;
        colbase = nt * 128;
        noff = 2048 + colbase;
    }
    gemm_h(A, nullptr, 1 << 30, 512, W, 512, 8, o, ldo, colbase, 0, rope, lts, t, e0,
           nullptr, stat, g_uv, noff);
}

// ============================================================================
// Launch. 3 launches: cvt_all (convert+zero+uv), k1, k3.
// ============================================================================
extern "C" void kernel_launch(void* const* d_in, const int* in_sizes, int n_in,
                              void* d_out, int out_size) {
    const float* x_src = (const float*)d_in[0];
    const float* x_dst = (const float*)d_in[1];
    const float* edge  = (const float*)d_in[2];
    const float* t     = (const float*)d_in[3];
    const float* Wqd   = (const float*)d_in[4];
    const float* qg    = (const float*)d_in[5];
    const float* qb    = (const float*)d_in[6];
    const float* Wqn   = (const float*)d_in[7];
    const float* Wqr   = (const float*)d_in[8];
    const float* Wkvd  = (const float*)d_in[9];
    const float* kvg   = (const float*)d_in[10];
    const float* kvb   = (const float*)d_in[11];
    const float* Wkn   = (const float*)d_in[12];
    const float* Wkr   = (const float*)d_in[13];
    const float* Wv    = (const float*)d_in[14];
    const float* qlts  = (const float*)d_in[15];
    const float* klts  = (const float*)d_in[16];
    float* out = (float*)d_out;

    static bool attr_set = false;
    if (!attr_set) {
        cudaFuncSetAttribute(mla_k1, cudaFuncAttributeMaxDynamicSharedMemorySize, SMEM_K1);
        cudaFuncSetAttribute(mla_k3, cudaFuncAttributeMaxDynamicSharedMemorySize, SMEM_K3);
        attr_set = true;
    }

    const int E = in_sizes[3];
    const long EX = (long)E * 1024;
    const size_t total_cvt = (size_t)(3 * EX) + OFF_END;
    const unsigned cvt_blocks  = (unsigned)(total_cvt / 4096);   // 16 floats/thread
    const unsigned zero_blocks = (unsigned)(E / 256);

    cvt_all<<<cvt_blocks + zero_blocks + UV_BLOCKS, 256>>>(
        x_src, x_dst, edge, Wqd, Wkvd, Wqn, Wqr, Wkn, Wkr, Wv,
        qg, qb, kvg, kvb, EX);
    mla_k1<<<8 * (E / 128), 256, SMEM_K1>>>(E);
    mla_k3<<<dim3(24, E / 128), 256, SMEM_K3>>>(t, qlts, klts, out, E);
}

// round 16
// speedup vs baseline: 1.0075x; 1.0058x over previous
#include <cuda_runtime.h>
#include <cuda_fp16.h>
#include <cstdint>

// ============================================================================
// Problem constants
// ============================================================================
static constexpr int EDGES_MAX = 65536;

// fp16 scratch: [x_src | x_dst | edge_emb], each E*1024
__device__ __align__(16) __half g_xh[(size_t)3 * EDGES_MAX * 1024];
// fp16 weights (gamma folded into up-projection weights), concatenated
__device__ __align__(16) __half g_wh[3145728];
// fp16 RAW down-projection outputs (no LN applied; LN folded into k3)
__device__ __align__(16) __half g_cQh [(size_t)EDGES_MAX * 512];
__device__ __align__(16) __half g_cKVh[(size_t)EDGES_MAX * 512];
// per-row (sum, sumsq) of raw down-proj outputs: rows [0,E) = Q, [E,2E) = KV
__device__ __align__(16) float2 g_stats[(size_t)2 * EDGES_MAX];
// per-output-channel (u, v): u = sum_k gamma_k W_nk, v = sum_k beta_k W_nk
// layout: [Wqn 512 | Wqr 512 | Wkn 512 | Wkr 512 | Wv 1024]
__device__ __align__(16) float2 g_uv[3072];

// weight offsets in g_wh (elements)
static constexpr size_t OFF_WQD  = 0;
static constexpr size_t OFF_WKVD = OFF_WQD  + (size_t)512 * 1024;   //  524288
static constexpr size_t OFF_WQN  = OFF_WKVD + (size_t)512 * 2048;   // 1572864
static constexpr size_t OFF_WQR  = OFF_WQN  + (size_t)512 * 512;
static constexpr size_t OFF_WKN  = OFF_WQR  + (size_t)512 * 512;
static constexpr size_t OFF_WKR  = OFF_WKN  + (size_t)512 * 512;
static constexpr size_t OFF_WV   = OFF_WKR  + (size_t)512 * 512;
static constexpr size_t OFF_END  = OFF_WV   + (size_t)1024 * 512;   // 3145728

// SMEM: per stage A[128x64 fp16]=16KB + B[128x64 fp16]=16KB, 3 stages.
static constexpr int STAGE_B = 32768;
static constexpr int STAGES  = 3;
static constexpr int PIPE_B  = STAGES * STAGE_B;          // 98304
static constexpr int SMEM_K1 = PIPE_B;
static constexpr int SMEM_K3 = PIPE_B + 128 * 16 * 8;     // + rope float2 table

// ============================================================================
// PTX helpers
// ============================================================================
__device__ __forceinline__ uint32_t smem_to_u32(const void* p) {
    uint32_t a;
    asm("{ .reg .u64 t; cvta.to.shared.u64 t, %1; cvt.u32.u64 %0, t; }" : "=r"(a) : "l"(p));
    return a;
}

#define CP_ASYNC16(dst_u32, src_ptr) \
    asm volatile("cp.async.cg.shared.global [%0], [%1], 16;" :: "r"(dst_u32), "l"(src_ptr))
#define CP_COMMIT() asm volatile("cp.async.commit_group;" ::: "memory")
#define CP_WAIT1()  asm volatile("cp.async.wait_group 1;"  ::: "memory")

__device__ __forceinline__ void ldsm_x4(uint32_t* r, uint32_t addr) {
    asm volatile("ldmatrix.sync.aligned.m8n8.x4.shared.b16 {%0,%1,%2,%3}, [%4];"
                 : "=r"(r[0]), "=r"(r[1]), "=r"(r[2]), "=r"(r[3]) : "r"(addr));
}

__device__ __forceinline__ void mma16816(float* d, const uint32_t* a, uint32_t b0, uint32_t b1) {
    asm volatile(
        "mma.sync.aligned.m16n8k16.row.col.f32.f16.f16.f32 "
        "{%0,%1,%2,%3}, {%4,%5,%6,%7}, {%8,%9}, {%0,%1,%2,%3};"
        : "+f"(d[0]), "+f"(d[1]), "+f"(d[2]), "+f"(d[3])
        : "r"(a[0]), "r"(a[1]), "r"(a[2]), "r"(a[3]), "r"(b0), "r"(b1));
}

// ============================================================================
// fp16 tile loader: 128 rows x 64 halves (128B/row), XOR-16B swizzle.
// ============================================================================
__device__ __forceinline__ void load_tile_h(uint32_t dst, const __half* __restrict__ src,
                                            long ld, int tid) {
    #pragma unroll
    for (int i = 0; i < 4; i++) {
        int idx = tid + i * 256;
        int row = idx >> 3, c = idx & 7;
        uint32_t d = dst + (uint32_t)(row * 128 + ((c ^ (row & 7)) << 4));
        CP_ASYNC16(d, src + (size_t)row * ld + c * 8);
    }
}

// ============================================================================
// Core: C[128,128] = A[128,K] * W[128,K]^T (fp16 in, fp32 accum)
// 8 warps 4(M) x 2(N), warp tile 32x64, K chunks of 64. 3-deep cp.async pipe.
// half_out: write raw fp16 + emit per-row (sum,sumsq) partials to stat_out.
// else:     apply per-row LN affine (stat_in + uv at noff) then optional RoPE,
//           streaming fp32 store.
// ============================================================================
__device__ void gemm_h(const __half* __restrict__ A0, const __half* __restrict__ A1,
                       int asplit, long lda,
                       const __half* __restrict__ W, long ldw, int nch,
                       void* __restrict__ outp, long ldo, int colbase, int half_out,
                       int rope, const float* __restrict__ lts,
                       const float* __restrict__ t, long e0,
                       float2* __restrict__ stat_out,          // prebased +e0 (k1)
                       const float2* __restrict__ stat_in,     // prebased +e0 (k3)
                       const float2* __restrict__ uv, int noff)
{
    extern __shared__ char smem[];
    const uint32_t su = smem_to_u32(smem);
    const int tid  = threadIdx.x;
    const int lane = tid & 31;
    const int wid  = tid >> 5, wm = wid & 3, wn = wid >> 2;
    const int l7   = lane & 7, sub = lane >> 3;
    const int khi  = sub >> 1;
    const int rsel = (sub & 1) * 8;

    float2* ropeTab = reinterpret_cast<float2*>(smem + PIPE_B);
    if (rope) {
        for (int idx = tid; idx < 128 * 16; idx += 256) {
            int row = idx >> 4, j = idx & 15;
            float ang = __ldg(t + e0 + row) / expf(__ldg(lts + j));
            float s, c;
            sincosf(ang, &s, &c);
            ropeTab[idx] = make_float2(c, s);
        }
    }

    float acc[2][8][4];
    #pragma unroll
    for (int a = 0; a < 2; a++)
        #pragma unroll
        for (int b = 0; b < 8; b++)
            #pragma unroll
            for (int c = 0; c < 4; c++) acc[a][b][c] = 0.f;

    uint32_t abase[2]; uint32_t a7[2];
    #pragma unroll
    for (int mf = 0; mf < 2; mf++) {
        int r = wm * 32 + mf * 16 + rsel + l7;
        a7[mf] = (uint32_t)(r & 7);
        abase[mf] = (uint32_t)(r * 128);
    }
    uint32_t bbase[4]; uint32_t b7[4];
    #pragma unroll
    for (int np = 0; np < 4; np++) {
        int r = wn * 64 + np * 16 + rsel + l7;
        b7[np] = (uint32_t)(r & 7);
        bbase[np] = (uint32_t)(r * 128);
    }

    auto a_src = [&](int c) -> const __half* {
        return (c < asplit) ? (A0 + (size_t)c * 64) : (A1 + (size_t)(c - asplit) * 64);
    };

    load_tile_h(su, a_src(0), lda, tid);
    load_tile_h(su + 16384, W, ldw, tid);
    CP_COMMIT();
    if (nch > 1) {
        load_tile_h(su + STAGE_B, a_src(1), lda, tid);
        load_tile_h(su + STAGE_B + 16384, W + 64, ldw, tid);
    }
    CP_COMMIT();

    for (int c = 0; c < nch; c++) {
        const int st = c % STAGES;
        CP_WAIT1();
        __syncthreads();
        if (c + 2 < nch) {
            const int s2 = (c + 2) % STAGES;
            load_tile_h(su + (uint32_t)(s2 * STAGE_B), a_src(c + 2), lda, tid);
            load_tile_h(su + (uint32_t)(s2 * STAGE_B + 16384), W + (size_t)(c + 2) * 64, ldw, tid);
        }
        CP_COMMIT();

        const uint32_t As = su + st * STAGE_B;
        const uint32_t Bs = As + 16384;
        #pragma unroll
        for (int ks = 0; ks < 4; ks++) {
            const uint32_t kb = (uint32_t)(ks * 2 + khi);
            uint32_t af[2][4];
            #pragma unroll
            for (int mf = 0; mf < 2; mf++)
                ldsm_x4(af[mf], As + abase[mf] + ((kb ^ a7[mf]) << 4));
            uint32_t bq[4][4];
            #pragma unroll
            for (int np = 0; np < 4; np++)
                ldsm_x4(bq[np], Bs + bbase[np] + ((kb ^ b7[np]) << 4));
            #pragma unroll
            for (int mf = 0; mf < 2; mf++)
                #pragma unroll
                for (int np = 0; np < 4; np++) {
                    mma16816(acc[mf][np * 2 + 0], af[mf], bq[np][0], bq[np][2]);
                    mma16816(acc[mf][np * 2 + 1], af[mf], bq[np][1], bq[np][3]);
                }
        }
    }

    const int gid = lane >> 2, tig = lane & 3;

    if (half_out) {
        // raw fp16 store + per-row (sum, sumsq) partial emission
        #pragma unroll
        for (int mf = 0; mf < 2; mf++) {
            #pragma unroll
            for (int rr = 0; rr < 2; rr++) {
                const int row = wm * 32 + mf * 16 + rr * 8 + gid;
                const size_t rb = (size_t)(e0 + row) * ldo + colbase;
                float s1 = 0.f, s2 = 0.f;
                #pragma unroll
                for (int nf = 0; nf < 8; nf++) {
                    const int col = wn * 64 + nf * 8 + tig * 2;
                    float x0 = acc[mf][nf][rr * 2 + 0];
                    float x1 = acc[mf][nf][rr * 2 + 1];
                    s1 += x0 + x1;
                    s2 += x0 * x0 + x1 * x1;
                    *reinterpret_cast<__half2*>(reinterpret_cast<__half*>(outp) + rb + col) =
                        __floats2half2_rn(x0, x1);
                }
                s1 += __shfl_xor_sync(0xFFFFFFFFu, s1, 1);
                s2 += __shfl_xor_sync(0xFFFFFFFFu, s2, 1);
                s1 += __shfl_xor_sync(0xFFFFFFFFu, s1, 2);
                s2 += __shfl_xor_sync(0xFFFFFFFFu, s2, 2);
                if (tig == 0) {
                    atomicAdd(&stat_out[row].x, s1);
                    atomicAdd(&stat_out[row].y, s2);
                }
            }
        }
    } else {
        // LN affine (+ optional RoPE) epilogue, streaming fp32 store
        float4 uvf[8];
        #pragma unroll
        for (int nf = 0; nf < 8; nf++) {
            const int col = wn * 64 + nf * 8 + tig * 2;
            uvf[nf] = *reinterpret_cast<const float4*>(&uv[noff + col]);
        }
        #pragma unroll
        for (int mf = 0; mf < 2; mf++) {
            #pragma unroll
            for (int rr = 0; rr < 2; rr++) {
                const int row = wm * 32 + mf * 16 + rr * 8 + gid;
                const size_t rb = (size_t)(e0 + row) * ldo + colbase;
                float2 st = stat_in[row];
                float mu   = st.x * (1.f / 512.f);
                float var  = st.y * (1.f / 512.f) - mu * mu;
                float rstd = rsqrtf(var + 1e-5f);
                float cm   = -rstd * mu;
                #pragma unroll
                for (int nf = 0; nf < 8; nf++) {
                    const int col = wn * 64 + nf * 8 + tig * 2;
                    float x0 = acc[mf][nf][rr * 2 + 0];
                    float x1 = acc[mf][nf][rr * 2 + 1];
                    x0 = fmaf(rstd, x0, fmaf(cm, uvf[nf].x, uvf[nf].y));
                    x1 = fmaf(rstd, x1, fmaf(cm, uvf[nf].z, uvf[nf].w));
                    if (rope) {
                        float2 cs = ropeTab[row * 16 + ((col & 31) >> 1)];
                        float y0 = x0 * cs.x - x1 * cs.y;
                        float y1 = x0 * cs.y + x1 * cs.x;
                        x0 = y0; x1 = y1;
                    }
                    __stcs(reinterpret_cast<float2*>(reinterpret_cast<float*>(outp) + rb + col),
                           make_float2(x0, x1));
                }
            }
        }
    }
}

// ============================================================================
// Prepass (ONE launch): grid = [convert blocks | stats-zero blocks | uv blocks]
//   convert: 16 floats/thread (MLP=4), gamma folded into up-weights
//   zero:    g_stats = 0
//   uv:      one warp per output channel n (384 blocks x 8 warps = 3072)
// ============================================================================
static constexpr unsigned UV_BLOCKS = 384;

__global__ void __launch_bounds__(256)
cvt_all(const float* __restrict__ x_src, const float* __restrict__ x_dst,
        const float* __restrict__ edge,
        const float* __restrict__ Wqd, const float* __restrict__ Wkvd,
        const float* __restrict__ Wqn, const float* __restrict__ Wqr,
        const float* __restrict__ Wkn, const float* __restrict__ Wkr,
        const float* __restrict__ Wv,
        const float* __restrict__ qg, const float* __restrict__ qb,
        const float* __restrict__ kvg, const float* __restrict__ kvb, long EX)
{
    const unsigned zb = (unsigned)(EX >> 18);              // E/256 zero blocks
    const unsigned zbase  = gridDim.x - UV_BLOCKS - zb;    // first zero block
    const unsigned uvbase = gridDim.x - UV_BLOCKS;         // first uv block

    if (blockIdx.x >= uvbase) {
        // ---- u,v per output channel ----
        const int n = (int)((blockIdx.x - uvbase) * 8 + (threadIdx.x >> 5));
        const int lane = threadIdx.x & 31;
        const float* wrow;
        const float *g, *b;
        if      (n < 512)  { wrow = Wqn + (size_t)n * 512;          g = qg;  b = qb;  }
        else if (n < 1024) { wrow = Wqr + (size_t)(n - 512) * 512;  g = qg;  b = qb;  }
        else if (n < 1536) { wrow = Wkn + (size_t)(n - 1024) * 512; g = kvg; b = kvb; }
        else if (n < 2048) { wrow = Wkr + (size_t)(n - 1536) * 512; g = kvg; b = kvb; }
        else               { wrow = Wv  + (size_t)(n - 2048) * 512; g = kvg; b = kvb; }
        float u = 0.f, v = 0.f;
        #pragma unroll
        for (int k = lane; k < 512; k += 32) {
            float w = wrow[k];
            u += w * g[k];
            v += w * b[k];
        }
        #pragma unroll
        for (int o = 16; o > 0; o >>= 1) {
            u += __shfl_xor_sync(0xFFFFFFFFu, u, o);
            v += __shfl_xor_sync(0xFFFFFFFFu, v, o);
        }
        if (lane == 0) g_uv[n] = make_float2(u, v);
        return;
    }
    if (blockIdx.x >= zbase) {
        size_t idx = (size_t)(blockIdx.x - zbase) * 256 + threadIdx.x;
        reinterpret_cast<float4*>(g_stats)[idx] = make_float4(0.f, 0.f, 0.f, 0.f);
        return;
    }

    // ---- convert: 16 floats per thread ----
    size_t i = ((size_t)blockIdx.x * 256 + threadIdx.x) * 16;
    const float* s;
    __half* d;
    const size_t AX = (size_t)EX;
    bool fold = false;
    const float* gam = nullptr;
    int gcol = 0;
    if (i < 3 * AX) {
        size_t r = i / AX;
        s = ((r == 0) ? x_src : (r == 1) ? x_dst : edge) + (i - r * AX);
        d = g_xh + i;
    } else {
        size_t j = i - 3 * AX;
        const size_t bounds[8] = { OFF_WQD, OFF_WKVD, OFF_WQN, OFF_WQR,
                                   OFF_WKN, OFF_WKR, OFF_WV, OFF_END };
        const float* srcs[7] = { Wqd, Wkvd, Wqn, Wqr, Wkn, Wkr, Wv };
        int r = 0;
        #pragma unroll
        for (int k = 1; k < 7; k++) r += (j >= bounds[k]);
        s = srcs[r] + (j - bounds[r]);
        d = g_wh + j;
        if (j >= OFF_WQN) {
            fold = true;
            gam = (j < OFF_WKN) ? qg : kvg;
            gcol = (int)(j & 511);
        }
    }
    float4 v[4];
    #pragma unroll
    for (int q = 0; q < 4; q++) v[q] = *reinterpret_cast<const float4*>(s + q * 4);
    if (fold) {
        #pragma unroll
        for (int q = 0; q < 4; q++) {
            float4 gq = *reinterpret_cast<const float4*>(gam + gcol + q * 4);
            v[q].x *= gq.x; v[q].y *= gq.y; v[q].z *= gq.z; v[q].w *= gq.w;
        }
    }
    __half2 h[8];
    #pragma unroll
    for (int q = 0; q < 4; q++) {
        h[q * 2 + 0] = __floats2half2_rn(v[q].x, v[q].y);
        h[q * 2 + 1] = __floats2half2_rn(v[q].z, v[q].w);
    }
    *reinterpret_cast<uint4*>(d)     = reinterpret_cast<uint4*>(h)[0];
    *reinterpret_cast<uint4*>(d + 8) = reinterpret_cast<uint4*>(h)[1];
}

// ============================================================================
// K1: down-projections (raw out + stats). KV CTAs first (long), then Q.
// ============================================================================
__global__ void __launch_bounds__(256, 2)
mla_k1(int E)
{
    const int kvctas = 4 * (E / 128);
    const int id = blockIdx.x;
    const __half* xs = g_xh;
    const __half* xd = g_xh + (size_t)E * 1024;
    const __half* xe = g_xh + (size_t)2 * E * 1024;
    if (id < kvctas) {
        const int seg = id & 3, mt = id >> 2;
        const long e0 = (long)mt * 128;
        gemm_h(xd + e0 * 1024, xe + e0 * 1024, 16, 1024,
               g_wh + OFF_WKVD + (size_t)seg * 128 * 2048, 2048, 32,
               g_cKVh, 512, seg * 128, 1, 0, nullptr, nullptr, e0,
               g_stats + E + e0, nullptr, nullptr, 0);
    } else {
        const int j = id - kvctas;
        const int seg = j & 3, mt = j >> 2;
        const long e0 = (long)mt * 128;
        gemm_h(xs + e0 * 1024, nullptr, 1 << 30, 1024,
               g_wh + OFF_WQD + (size_t)seg * 128 * 1024, 1024, 16,
               g_cQh, 512, seg * 128, 1, 0, nullptr, nullptr, e0,
               g_stats + e0, nullptr, nullptr, 0);
    }
}

// ============================================================================
// K3: up-projections on RAW scratch + fused LN affine + RoPE.
// grid (24, tiles): x = segment (fast).
// ============================================================================
__global__ void __launch_bounds__(256, 2)
mla_k3(const float* __restrict__ t,
       const float* __restrict__ qlts, const float* __restrict__ klts,
       float* __restrict__ out, int E)
{
    const int y = blockIdx.x;
    const long e0 = (long)blockIdx.y * 128;
    const long S = (long)E * 512;

    const __half* A;
    const __half* W;
    float* o;
    long ldo;
    int colbase, rope = 0, noff;
    const float* lts = nullptr;
    const float2* stat;

    if (y < 16) {
        const int seg = y >> 2, nt = y & 3;
        A = ((seg < 2) ? g_cQh : g_cKVh) + e0 * 512;
        stat = g_stats + ((seg < 2) ? 0 : E) + e0;
        const size_t offs[4] = { OFF_WQN, OFF_WQR, OFF_WKN, OFF_WKR };
        W = g_wh + offs[seg] + (size_t)nt * 128 * 512;
        o = out + (long)seg * S;
        ldo = 512;
        colbase = nt * 128;
        noff = seg * 512 + colbase;
        if (seg == 1) { rope = 1; lts = qlts; }
        if (seg == 3) { rope = 1; lts = klts; }
    } else {
        const int nt = y - 16;
        A = g_cKVh + e0 * 512;
        stat = g_stats + E + e0;
        W = g_wh + OFF_WV + (size_t)nt * 128 * 512;
        o = out + 4 * S;
        ldo = 1024;
        colbase = nt * 128;
        noff = 2048 + colbase;
    }
    gemm_h(A, nullptr, 1 << 30, 512, W, 512, 8, o, ldo, colbase, 0, rope, lts, t, e0,
           nullptr, stat, g_uv, noff);
}

// ============================================================================
// Launch. 3 launches: cvt_all (convert+zero+uv), k1, k3.
// ============================================================================
extern "C" void kernel_launch(void* const* d_in, const int* in_sizes, int n_in,
                              void* d_out, int out_size) {
    const float* x_src = (const float*)d_in[0];
    const float* x_dst = (const float*)d_in[1];
    const float* edge  = (const float*)d_in[2];
    const float* t     = (const float*)d_in[3];
    const float* Wqd   = (const float*)d_in[4];
    const float* qg    = (const float*)d_in[5];
    const float* qb    = (const float*)d_in[6];
    const float* Wqn   = (const float*)d_in[7];
    const float* Wqr   = (const float*)d_in[8];
    const float* Wkvd  = (const float*)d_in[9];
    const float* kvg   = (const float*)d_in[10];
    const float* kvb   = (const float*)d_in[11];
    const float* Wkn   = (const float*)d_in[12];
    const float* Wkr   = (const float*)d_in[13];
    const float* Wv    = (const float*)d_in[14];
    const float* qlts  = (const float*)d_in[15];
    const float* klts  = (const float*)d_in[16];
    float* out = (float*)d_out;

    static bool attr_set = false;
    if (!attr_set) {
        cudaFuncSetAttribute(mla_k1, cudaFuncAttributeMaxDynamicSharedMemorySize, SMEM_K1);
        cudaFuncSetAttribute(mla_k3, cudaFuncAttributeMaxDynamicSharedMemorySize, SMEM_K3);
        attr_set = true;
    }

    const int E = in_sizes[3];
    const long EX = (long)E * 1024;
    const size_t total_cvt = (size_t)(3 * EX) + OFF_END;
    const unsigned cvt_blocks  = (unsigned)(total_cvt / 4096);   // 16 floats/thread
    const unsigned zero_blocks = (unsigned)(E / 256);

    cvt_all<<<cvt_blocks + zero_blocks + UV_BLOCKS, 256>>>(
        x_src, x_dst, edge, Wqd, Wkvd, Wqn, Wqr, Wkn, Wkr, Wv,
        qg, qb, kvg, kvb, EX);
    mla_k1<<<8 * (E / 128), 256, SMEM_K1>>>(E);
    mla_k3<<<dim3(24, E / 128), 256, SMEM_K3>>>(t, qlts, klts, out, E);
}

// round 17
// speedup vs baseline: 1.0082x; 1.0008x over previous
#include <cuda_runtime.h>
#include <cuda_fp16.h>
#include <cstdint>

// ============================================================================
// Problem constants
// ============================================================================
static constexpr int EDGES_MAX = 65536;

// fp16 scratch: [x_src | x_dst | edge_emb], each E*1024
__device__ __align__(16) __half g_xh[(size_t)3 * EDGES_MAX * 1024];
// fp16 weights (gamma folded into up-projection weights), concatenated
__device__ __align__(16) __half g_wh[3145728];
// fp16 RAW down-projection outputs (no LN applied; LN folded into k3)
__device__ __align__(16) __half g_cQh [(size_t)EDGES_MAX * 512];
__device__ __align__(16) __half g_cKVh[(size_t)EDGES_MAX * 512];
// per-row (sum, sumsq) of raw down-proj outputs: rows [0,E) = Q, [E,2E) = KV
__device__ __align__(16) float2 g_stats[(size_t)2 * EDGES_MAX];
// per-output-channel (u, v): u = sum_k gamma_k W_nk, v = sum_k beta_k W_nk
// layout: [Wqn 512 | Wqr 512 | Wkn 512 | Wkr 512 | Wv 1024]
__device__ __align__(16) float2 g_uv[3072];

// weight offsets in g_wh (elements)
static constexpr size_t OFF_WQD  = 0;
static constexpr size_t OFF_WKVD = OFF_WQD  + (size_t)512 * 1024;   //  524288
static constexpr size_t OFF_WQN  = OFF_WKVD + (size_t)512 * 2048;   // 1572864
static constexpr size_t OFF_WQR  = OFF_WQN  + (size_t)512 * 512;
static constexpr size_t OFF_WKN  = OFF_WQR  + (size_t)512 * 512;
static constexpr size_t OFF_WKR  = OFF_WKN  + (size_t)512 * 512;
static constexpr size_t OFF_WV   = OFF_WKR  + (size_t)512 * 512;
static constexpr size_t OFF_END  = OFF_WV   + (size_t)1024 * 512;   // 3145728

// SMEM: per stage A[128x64 fp16]=16KB + B[128x64 fp16]=16KB, 3 stages.
static constexpr int STAGE_B = 32768;
static constexpr int STAGES  = 3;
static constexpr int PIPE_B  = STAGES * STAGE_B;          // 98304
static constexpr int SMEM_K1 = PIPE_B;
static constexpr int SMEM_K3 = PIPE_B + 128 * 16 * 8;     // + rope float2 table

// ============================================================================
// PTX helpers
// ============================================================================
__device__ __forceinline__ uint32_t smem_to_u32(const void* p) {
    uint32_t a;
    asm("{ .reg .u64 t; cvta.to.shared.u64 t, %1; cvt.u32.u64 %0, t; }" : "=r"(a) : "l"(p));
    return a;
}

#define CP_ASYNC16(dst_u32, src_ptr) \
    asm volatile("cp.async.cg.shared.global [%0], [%1], 16;" :: "r"(dst_u32), "l"(src_ptr))
#define CP_COMMIT() asm volatile("cp.async.commit_group;" ::: "memory")
#define CP_WAIT1()  asm volatile("cp.async.wait_group 1;"  ::: "memory")

__device__ __forceinline__ void ldsm_x4(uint32_t* r, uint32_t addr) {
    asm volatile("ldmatrix.sync.aligned.m8n8.x4.shared.b16 {%0,%1,%2,%3}, [%4];"
                 : "=r"(r[0]), "=r"(r[1]), "=r"(r[2]), "=r"(r[3]) : "r"(addr));
}

__device__ __forceinline__ void mma16816(float* d, const uint32_t* a, uint32_t b0, uint32_t b1) {
    asm volatile(
        "mma.sync.aligned.m16n8k16.row.col.f32.f16.f16.f32 "
        "{%0,%1,%2,%3}, {%4,%5,%6,%7}, {%8,%9}, {%0,%1,%2,%3};"
        : "+f"(d[0]), "+f"(d[1]), "+f"(d[2]), "+f"(d[3])
        : "r"(a[0]), "r"(a[1]), "r"(a[2]), "r"(a[3]), "r"(b0), "r"(b1));
}

// ============================================================================
// fp16 tile loader: 128 rows x 64 halves (128B/row), XOR-16B swizzle.
// ============================================================================
__device__ __forceinline__ void load_tile_h(uint32_t dst, const __half* __restrict__ src,
                                            long ld, int tid) {
    #pragma unroll
    for (int i = 0; i < 4; i++) {
        int idx = tid + i * 256;
        int row = idx >> 3, c = idx & 7;
        uint32_t d = dst + (uint32_t)(row * 128 + ((c ^ (row & 7)) << 4));
        CP_ASYNC16(d, src + (size_t)row * ld + c * 8);
    }
}

// ============================================================================
// Core: C[128,128] = A[128,K] * W[128,K]^T (fp16 in, fp32 accum)
// 8 warps 4(M) x 2(N), warp tile 32x64, K chunks of 64. 3-deep cp.async pipe.
// half_out: write raw fp16 + emit per-row (sum,sumsq) partials to stat_out.
// else:     apply per-row LN affine (stat_in + uv at noff) then optional RoPE,
//           streaming fp32 store.
// RoPE table build is deferred until AFTER prologue load issue so its MUFU
// chain hides under the cp.async fill latency.
// ============================================================================
__device__ void gemm_h(const __half* __restrict__ A0, const __half* __restrict__ A1,
                       int asplit, long lda,
                       const __half* __restrict__ W, long ldw, int nch,
                       void* __restrict__ outp, long ldo, int colbase, int half_out,
                       int rope, const float* __restrict__ lts,
                       const float* __restrict__ t, long e0,
                       float2* __restrict__ stat_out,          // prebased +e0 (k1)
                       const float2* __restrict__ stat_in,     // prebased +e0 (k3)
                       const float2* __restrict__ uv, int noff)
{
    extern __shared__ char smem[];
    const uint32_t su = smem_to_u32(smem);
    const int tid  = threadIdx.x;
    const int lane = tid & 31;
    const int wid  = tid >> 5, wm = wid & 3, wn = wid >> 2;
    const int l7   = lane & 7, sub = lane >> 3;
    const int khi  = sub >> 1;
    const int rsel = (sub & 1) * 8;

    float acc[2][8][4];
    #pragma unroll
    for (int a = 0; a < 2; a++)
        #pragma unroll
        for (int b = 0; b < 8; b++)
            #pragma unroll
            for (int c = 0; c < 4; c++) acc[a][b][c] = 0.f;

    uint32_t abase[2]; uint32_t a7[2];
    #pragma unroll
    for (int mf = 0; mf < 2; mf++) {
        int r = wm * 32 + mf * 16 + rsel + l7;
        a7[mf] = (uint32_t)(r & 7);
        abase[mf] = (uint32_t)(r * 128);
    }
    uint32_t bbase[4]; uint32_t b7[4];
    #pragma unroll
    for (int np = 0; np < 4; np++) {
        int r = wn * 64 + np * 16 + rsel + l7;
        b7[np] = (uint32_t)(r & 7);
        bbase[np] = (uint32_t)(r * 128);
    }

    auto a_src = [&](int c) -> const __half* {
        return (c < asplit) ? (A0 + (size_t)c * 64) : (A1 + (size_t)(c - asplit) * 64);
    };

    // Prologue: issue stages 0,1 FIRST so DRAM fill starts immediately.
    load_tile_h(su, a_src(0), lda, tid);
    load_tile_h(su + 16384, W, ldw, tid);
    CP_COMMIT();
    if (nch > 1) {
        load_tile_h(su + STAGE_B, a_src(1), lda, tid);
        load_tile_h(su + STAGE_B + 16384, W + 64, ldw, tid);
    }
    CP_COMMIT();

    // RoPE table build now overlaps the fill (first read is in the epilogue,
    // behind multiple __syncthreads).
    float2* ropeTab = reinterpret_cast<float2*>(smem + PIPE_B);
    if (rope) {
        for (int idx = tid; idx < 128 * 16; idx += 256) {
            int row = idx >> 4, j = idx & 15;
            float ang = __ldg(t + e0 + row) / expf(__ldg(lts + j));
            float s, c;
            sincosf(ang, &s, &c);
            ropeTab[idx] = make_float2(c, s);
        }
    }

    for (int c = 0; c < nch; c++) {
        const int st = c % STAGES;
        CP_WAIT1();
        __syncthreads();
        if (c + 2 < nch) {
            const int s2 = (c + 2) % STAGES;
            load_tile_h(su + (uint32_t)(s2 * STAGE_B), a_src(c + 2), lda, tid);
            load_tile_h(su + (uint32_t)(s2 * STAGE_B + 16384), W + (size_t)(c + 2) * 64, ldw, tid);
        }
        CP_COMMIT();

        const uint32_t As = su + st * STAGE_B;
        const uint32_t Bs = As + 16384;
        #pragma unroll
        for (int ks = 0; ks < 4; ks++) {
            const uint32_t kb = (uint32_t)(ks * 2 + khi);
            uint32_t af[2][4];
            #pragma unroll
            for (int mf = 0; mf < 2; mf++)
                ldsm_x4(af[mf], As + abase[mf] + ((kb ^ a7[mf]) << 4));
            uint32_t bq[4][4];
            #pragma unroll
            for (int np = 0; np < 4; np++)
                ldsm_x4(bq[np], Bs + bbase[np] + ((kb ^ b7[np]) << 4));
            #pragma unroll
            for (int mf = 0; mf < 2; mf++)
                #pragma unroll
                for (int np = 0; np < 4; np++) {
                    mma16816(acc[mf][np * 2 + 0], af[mf], bq[np][0], bq[np][2]);
                    mma16816(acc[mf][np * 2 + 1], af[mf], bq[np][1], bq[np][3]);
                }
        }
    }

    const int gid = lane >> 2, tig = lane & 3;

    if (half_out) {
        // raw fp16 store + per-row (sum, sumsq) partial emission
        #pragma unroll
        for (int mf = 0; mf < 2; mf++) {
            #pragma unroll
            for (int rr = 0; rr < 2; rr++) {
                const int row = wm * 32 + mf * 16 + rr * 8 + gid;
                const size_t rb = (size_t)(e0 + row) * ldo + colbase;
                float s1 = 0.f, s2 = 0.f;
                #pragma unroll
                for (int nf = 0; nf < 8; nf++) {
                    const int col = wn * 64 + nf * 8 + tig * 2;
                    float x0 = acc[mf][nf][rr * 2 + 0];
                    float x1 = acc[mf][nf][rr * 2 + 1];
                    s1 += x0 + x1;
                    s2 += x0 * x0 + x1 * x1;
                    *reinterpret_cast<__half2*>(reinterpret_cast<__half*>(outp) + rb + col) =
                        __floats2half2_rn(x0, x1);
                }
                s1 += __shfl_xor_sync(0xFFFFFFFFu, s1, 1);
                s2 += __shfl_xor_sync(0xFFFFFFFFu, s2, 1);
                s1 += __shfl_xor_sync(0xFFFFFFFFu, s1, 2);
                s2 += __shfl_xor_sync(0xFFFFFFFFu, s2, 2);
                if (tig == 0) {
                    atomicAdd(&stat_out[row].x, s1);
                    atomicAdd(&stat_out[row].y, s2);
                }
            }
        }
    } else {
        // LN affine (+ optional RoPE) epilogue, streaming fp32 store
        float4 uvf[8];
        #pragma unroll
        for (int nf = 0; nf < 8; nf++) {
            const int col = wn * 64 + nf * 8 + tig * 2;
            uvf[nf] = *reinterpret_cast<const float4*>(&g_uv[noff + col]);
        }
        (void)uv;
        float2* ropeT = reinterpret_cast<float2*>(smem + PIPE_B);
        #pragma unroll
        for (int mf = 0; mf < 2; mf++) {
            #pragma unroll
            for (int rr = 0; rr < 2; rr++) {
                const int row = wm * 32 + mf * 16 + rr * 8 + gid;
                const size_t rb = (size_t)(e0 + row) * ldo + colbase;
                float2 st = stat_in[row];
                float mu   = st.x * (1.f / 512.f);
                float var  = st.y * (1.f / 512.f) - mu * mu;
                float rstd = rsqrtf(var + 1e-5f);
                float cm   = -rstd * mu;
                #pragma unroll
                for (int nf = 0; nf < 8; nf++) {
                    const int col = wn * 64 + nf * 8 + tig * 2;
                    float x0 = acc[mf][nf][rr * 2 + 0];
                    float x1 = acc[mf][nf][rr * 2 + 1];
                    x0 = fmaf(rstd, x0, fmaf(cm, uvf[nf].x, uvf[nf].y));
                    x1 = fmaf(rstd, x1, fmaf(cm, uvf[nf].z, uvf[nf].w));
                    if (rope) {
                        float2 cs = ropeT[row * 16 + ((col & 31) >> 1)];
                        float y0 = x0 * cs.x - x1 * cs.y;
                        float y1 = x0 * cs.y + x1 * cs.x;
                        x0 = y0; x1 = y1;
                    }
                    __stcs(reinterpret_cast<float2*>(reinterpret_cast<float*>(outp) + rb + col),
                           make_float2(x0, x1));
                }
            }
        }
    }
}

// ============================================================================
// Prepass (ONE launch): grid = [convert blocks | stats-zero blocks | uv blocks]
//   convert: 16 floats/thread (MLP=4), gamma folded into up-weights,
//            streaming loads (.cs) + streaming stores (.cs)
//   zero:    g_stats = 0
//   uv:      one warp per output channel n (384 blocks x 8 warps = 3072)
// ============================================================================
static constexpr unsigned UV_BLOCKS = 384;

__global__ void __launch_bounds__(256)
cvt_all(const float* __restrict__ x_src, const float* __restrict__ x_dst,
        const float* __restrict__ edge,
        const float* __restrict__ Wqd, const float* __restrict__ Wkvd,
        const float* __restrict__ Wqn, const float* __restrict__ Wqr,
        const float* __restrict__ Wkn, const float* __restrict__ Wkr,
        const float* __restrict__ Wv,
        const float* __restrict__ qg, const float* __restrict__ qb,
        const float* __restrict__ kvg, const float* __restrict__ kvb, long EX)
{
    const unsigned zb = (unsigned)(EX >> 18);              // E/256 zero blocks
    const unsigned zbase  = gridDim.x - UV_BLOCKS - zb;    // first zero block
    const unsigned uvbase = gridDim.x - UV_BLOCKS;         // first uv block

    if (blockIdx.x >= uvbase) {
        // ---- u,v per output channel ----
        const int n = (int)((blockIdx.x - uvbase) * 8 + (threadIdx.x >> 5));
        const int lane = threadIdx.x & 31;
        const float* wrow;
        const float *g, *b;
        if      (n < 512)  { wrow = Wqn + (size_t)n * 512;          g = qg;  b = qb;  }
        else if (n < 1024) { wrow = Wqr + (size_t)(n - 512) * 512;  g = qg;  b = qb;  }
        else if (n < 1536) { wrow = Wkn + (size_t)(n - 1024) * 512; g = kvg; b = kvb; }
        else if (n < 2048) { wrow = Wkr + (size_t)(n - 1536) * 512; g = kvg; b = kvb; }
        else               { wrow = Wv  + (size_t)(n - 2048) * 512; g = kvg; b = kvb; }
        float u = 0.f, v = 0.f;
        #pragma unroll
        for (int k = lane; k < 512; k += 32) {
            float w = wrow[k];
            u += w * g[k];
            v += w * b[k];
        }
        #pragma unroll
        for (int o = 16; o > 0; o >>= 1) {
            u += __shfl_xor_sync(0xFFFFFFFFu, u, o);
            v += __shfl_xor_sync(0xFFFFFFFFu, v, o);
        }
        if (lane == 0) g_uv[n] = make_float2(u, v);
        return;
    }
    if (blockIdx.x >= zbase) {
        size_t idx = (size_t)(blockIdx.x - zbase) * 256 + threadIdx.x;
        reinterpret_cast<float4*>(g_stats)[idx] = make_float4(0.f, 0.f, 0.f, 0.f);
        return;
    }

    // ---- convert: 16 floats per thread, streaming hints ----
    size_t i = ((size_t)blockIdx.x * 256 + threadIdx.x) * 16;
    const float* s;
    __half* d;
    const size_t AX = (size_t)EX;
    bool fold = false;
    const float* gam = nullptr;
    int gcol = 0;
    if (i < 3 * AX) {
        size_t r = i / AX;
        s = ((r == 0) ? x_src : (r == 1) ? x_dst : edge) + (i - r * AX);
        d = g_xh + i;
    } else {
        size_t j = i - 3 * AX;
        const size_t bounds[8] = { OFF_WQD, OFF_WKVD, OFF_WQN, OFF_WQR,
                                   OFF_WKN, OFF_WKR, OFF_WV, OFF_END };
        const float* srcs[7] = { Wqd, Wkvd, Wqn, Wqr, Wkn, Wkr, Wv };
        int r = 0;
        #pragma unroll
        for (int k = 1; k < 7; k++) r += (j >= bounds[k]);
        s = srcs[r] + (j - bounds[r]);
        d = g_wh + j;
        if (j >= OFF_WQN) {
            fold = true;
            gam = (j < OFF_WKN) ? qg : kvg;
            gcol = (int)(j & 511);
        }
    }
    float4 v[4];
    #pragma unroll
    for (int q = 0; q < 4; q++) v[q] = __ldcs(reinterpret_cast<const float4*>(s + q * 4));
    if (fold) {
        #pragma unroll
        for (int q = 0; q < 4; q++) {
            float4 gq = *reinterpret_cast<const float4*>(gam + gcol + q * 4);
            v[q].x *= gq.x; v[q].y *= gq.y; v[q].z *= gq.z; v[q].w *= gq.w;
        }
    }
    __half2 h[8];
    #pragma unroll
    for (int q = 0; q < 4; q++) {
        h[q * 2 + 0] = __floats2half2_rn(v[q].x, v[q].y);
        h[q * 2 + 1] = __floats2half2_rn(v[q].z, v[q].w);
    }
    __stcs(reinterpret_cast<uint4*>(d),     reinterpret_cast<uint4*>(h)[0]);
    __stcs(reinterpret_cast<uint4*>(d + 8), reinterpret_cast<uint4*>(h)[1]);
}

// ============================================================================
// K1: down-projections (raw out + stats). KV CTAs first (long), then Q.
// ============================================================================
__global__ void __launch_bounds__(256, 2)
mla_k1(int E)
{
    const int kvctas = 4 * (E / 128);
    const int id = blockIdx.x;
    const __half* xs = g_xh;
    const __half* xd = g_xh + (size_t)E * 1024;
    const __half* xe = g_xh + (size_t)2 * E * 1024;
    if (id < kvctas) {
        const int seg = id & 3, mt = id >> 2;
        const long e0 = (long)mt * 128;
        gemm_h(xd + e0 * 1024, xe + e0 * 1024, 16, 1024,
               g_wh + OFF_WKVD + (size_t)seg * 128 * 2048, 2048, 32,
               g_cKVh, 512, seg * 128, 1, 0, nullptr, nullptr, e0,
               g_stats + E + e0, nullptr, nullptr, 0);
    } else {
        const int j = id - kvctas;
        const int seg = j & 3, mt = j >> 2;
        const long e0 = (long)mt * 128;
        gemm_h(xs + e0 * 1024, nullptr, 1 << 30, 1024,
               g_wh + OFF_WQD + (size_t)seg * 128 * 1024, 1024, 16,
               g_cQh, 512, seg * 128, 1, 0, nullptr, nullptr, e0,
               g_stats + e0, nullptr, nullptr, 0);
    }
}

// ============================================================================
// K3: up-projections on RAW scratch + fused LN affine + RoPE.
// grid (24, tiles): x = segment (fast).
// ============================================================================
__global__ void __launch_bounds__(256, 2)
mla_k3(const float* __restrict__ t,
       const float* __restrict__ qlts, const float* __restrict__ klts,
       float* __restrict__ out, int E)
{
    const int y = blockIdx.x;
    const long e0 = (long)blockIdx.y * 128;
    const long S = (long)E * 512;

    const __half* A;
    const __half* W;
    float* o;
    long ldo;
    int colbase, rope = 0, noff;
    const float* lts = nullptr;
    const float2* stat;

    if (y < 16) {
        const int seg = y >> 2, nt = y & 3;
        A = ((seg < 2) ? g_cQh : g_cKVh) + e0 * 512;
        stat = g_stats + ((seg < 2) ? 0 : E) + e0;
        const size_t offs[4] = { OFF_WQN, OFF_WQR, OFF_WKN, OFF_WKR };
        W = g_wh + offs[seg] + (size_t)nt * 128 * 512;
        o = out + (long)seg * S;
        ldo = 512;
        colbase = nt * 128;
        noff = seg * 512 + colbase;
        if (seg == 1) { rope = 1; lts = qlts; }
        if (seg == 3) { rope = 1; lts = klts; }
    } else {
        const int nt = y - 16;
        A = g_cKVh + e0 * 512;
        stat = g_stats + E + e0;
        W = g_wh + OFF_WV + (size_t)nt * 128 * 512;
        o = out + 4 * S;
        ldo = 1024;
        colbase = nt * 128;
        noff = 2048 + colbase;
    }
    gemm_h(A, nullptr, 1 << 30, 512, W, 512, 8, o, ldo, colbase, 0, rope, lts, t, e0,
           nullptr, stat, g_uv, noff);
}

// ============================================================================
// Launch. 3 launches: cvt_all (convert+zero+uv), k1, k3.
// ============================================================================
extern "C" void kernel_launch(void* const* d_in, const int* in_sizes, int n_in,
                              void* d_out, int out_size) {
    const float* x_src = (const float*)d_in[0];
    const float* x_dst = (const float*)d_in[1];
    const float* edge  = (const float*)d_in[2];
    const float* t     = (const float*)d_in[3];
    const float* Wqd   = (const float*)d_in[4];
    const float* qg    = (const float*)d_in[5];
    const float* qb    = (const float*)d_in[6];
    const float* Wqn   = (const float*)d_in[7];
    const float* Wqr   = (const float*)d_in[8];
    const float* Wkvd  = (const float*)d_in[9];
    const float* kvg   = (const float*)d_in[10];
    const float* kvb   = (const float*)d_in[11];
    const float* Wkn   = (const float*)d_in[12];
    const float* Wkr   = (const float*)d_in[13];
    const float* Wv    = (const float*)d_in[14];
    const float* qlts  = (const float*)d_in[15];
    const float* klts  = (const float*)d_in[16];
    float* out = (float*)d_out;

    static bool attr_set = false;
    if (!attr_set) {
        cudaFuncSetAttribute(mla_k1, cudaFuncAttributeMaxDynamicSharedMemorySize, SMEM_K1);
        cudaFuncSetAttribute(mla_k3, cudaFuncAttributeMaxDynamicSharedMemorySize, SMEM_K3);
        attr_set = true;
    }

    const int E = in_sizes[3];
    const long EX = (long)E * 1024;
    const size_t total_cvt = (size_t)(3 * EX) + OFF_END;
    const unsigned cvt_blocks  = (unsigned)(total_cvt / 4096);   // 16 floats/thread
    const unsigned zero_blocks = (unsigned)(E / 256);

    cvt_all<<<cvt_blocks + zero_blocks + UV_BLOCKS, 256>>>(
        x_src, x_dst, edge, Wqd, Wkvd, Wqn, Wqr, Wkn, Wkr, Wv,
        qg, qb, kvg, kvb, EX);
    mla_k1<<<8 * (E / 128), 256, SMEM_K1>>>(E);
    mla_k3<<<dim3(24, E / 128), 256, SMEM_K3>>>(t, qlts, klts, out, E);
}